// round 5
// baseline (speedup 1.0000x reference)
#include <cuda_runtime.h>
#include <cuda_bf16.h>

#define EPS_SIGN 1e-8f
#define EPS_NORM 1e-9f

// Padded xyz as float4: each node gather = ONE LDG.128 = 1 L1 wavefront.
// __device__ global = sanctioned scratch (no allocation).
#define XYZ4_CAP 131072
__device__ float4 g_xyz4[XYZ4_CAP];

__global__ __launch_bounds__(256)
void repack_xyz_kernel(const float* __restrict__ xyz, int N)
{
    for (int i = blockIdx.x * blockDim.x + threadIdx.x;
         i < N;
         i += gridDim.x * blockDim.x)
    {
        g_xyz4[i] = make_float4(xyz[3*i + 0], xyz[3*i + 1], xyz[3*i + 2], 0.0f);
    }
}

// 1 edge per thread: minimal registers -> full occupancy, MLP_p1=2 ->
// minimal cross-CTA L1tex-queue spread. Gather wavefront count is
// invariant to edges/thread, so this trades nothing on the binding floor.
__global__ __launch_bounds__(256)
void edge_min_image_kernel(const int*   __restrict__ src,
                           const int*   __restrict__ dst,
                           const float* __restrict__ cell,
                           float* __restrict__ out_dis,
                           float* __restrict__ out_vec,
                           int E)
{
    int e = blockIdx.x * blockDim.x + threadIdx.x;
    if (e >= E) return;

    const float cx = __ldg(&cell[0]);
    const float cy = __ldg(&cell[1]);
    const float cz = __ldg(&cell[2]);

    int si = __ldg(&src[e]);
    int di = __ldg(&dst[e]);

    float4 a = g_xyz4[si];   // LDG.128, 1 wavefront
    float4 b = g_xyz4[di];   // LDG.128, 1 wavefront

    float dx = a.x - b.x;
    float dy = a.y - b.y;
    float dz = a.z - b.z;

    float ax = fabsf(dx), ay = fabsf(dy), az = fabsf(dz);

    // min-image component
    float mx = fminf(cx - ax, ax);
    float my = fminf(cy - ay, ay);
    float mz = fminf(cz - az, az);

    // mask2: +1 if min-image kept the original magnitude, else -1
    float k2x = (fabsf(mx) == ax) ? 1.0f : -1.0f;
    float k2y = (fabsf(my) == ay) ? 1.0f : -1.0f;
    float k2z = (fabsf(mz) == az) ? 1.0f : -1.0f;

    // sign of (d + eps): exact +-1 via compare-select (== t/|t|)
    float sx = (dx + EPS_SIGN >= 0.0f) ? 1.0f : -1.0f;
    float sy = (dy + EPS_SIGN >= 0.0f) ? 1.0f : -1.0f;
    float sz = (dz + EPS_SIGN >= 0.0f) ? 1.0f : -1.0f;

    // norm of the ORIGINAL (non-min-image) vector, + eps
    float ex = dx + EPS_NORM, ey = dy + EPS_NORM, ez = dz + EPS_NORM;
    out_dis[e] = sqrtf(ex*ex + ey*ey + ez*ez);

    float* vp = out_vec + 3*e;
    vp[0] = mx * (k2x * sx);
    vp[1] = my * (k2y * sy);
    vp[2] = mz * (k2z * sz);
}

// Fallback (N > scratch capacity): scalar-gather path, always correct.
__global__ __launch_bounds__(256)
void edge_min_image_fallback(const float* __restrict__ xyz,
                             const int*   __restrict__ src,
                             const int*   __restrict__ dst,
                             const float* __restrict__ cell,
                             float* __restrict__ out_dis,
                             float* __restrict__ out_vec,
                             int E)
{
    const float cx = __ldg(&cell[0]);
    const float cy = __ldg(&cell[1]);
    const float cz = __ldg(&cell[2]);

    int e = blockIdx.x * blockDim.x + threadIdx.x;
    if (e >= E) return;

    int si = src[e], di = dst[e];
    float dx = xyz[3*si+0] - xyz[3*di+0];
    float dy = xyz[3*si+1] - xyz[3*di+1];
    float dz = xyz[3*si+2] - xyz[3*di+2];

    float ax = fabsf(dx), ay = fabsf(dy), az = fabsf(dz);
    float mx = fminf(cx - ax, ax);
    float my = fminf(cy - ay, ay);
    float mz = fminf(cz - az, az);
    float k2x = (fabsf(mx) == ax) ? 1.0f : -1.0f;
    float k2y = (fabsf(my) == ay) ? 1.0f : -1.0f;
    float k2z = (fabsf(mz) == az) ? 1.0f : -1.0f;
    float sx = (dx + EPS_SIGN >= 0.0f) ? 1.0f : -1.0f;
    float sy = (dy + EPS_SIGN >= 0.0f) ? 1.0f : -1.0f;
    float sz = (dz + EPS_SIGN >= 0.0f) ? 1.0f : -1.0f;

    out_vec[3*e+0] = mx * (k2x * sx);
    out_vec[3*e+1] = my * (k2y * sy);
    out_vec[3*e+2] = mz * (k2z * sz);

    float ex = dx + EPS_NORM, ey = dy + EPS_NORM, ez = dz + EPS_NORM;
    out_dis[e] = sqrtf(ex*ex + ey*ey + ez*ez);
}

extern "C" void kernel_launch(void* const* d_in, const int* in_sizes, int n_in,
                              void* d_out, int out_size)
{
    const float* xyz  = (const float*)d_in[0];
    const int*   src  = (const int*)  d_in[1];
    const int*   dst  = (const int*)  d_in[2];
    const float* cell = (const float*)d_in[3];

    int N = in_sizes[0] / 3;   // xyz rows
    int E = in_sizes[1];       // number of edges

    float* out_dis = (float*)d_out;   // [E]
    float* out_vec = out_dis + E;     // [E,3] row-major

    const int t = 256;
    if (N <= XYZ4_CAP) {
        int rblocks = (N + t - 1) / t;
        if (rblocks > 1184) rblocks = 1184;  // grid-stride covers the rest
        repack_xyz_kernel<<<rblocks, t>>>(xyz, N);
        edge_min_image_kernel<<<(E + t - 1) / t, t>>>(src, dst, cell,
                                                      out_dis, out_vec, E);
    } else {
        edge_min_image_fallback<<<(E + t - 1) / t, t>>>(xyz, src, dst, cell,
                                                        out_dis, out_vec, E);
    }
}

// round 6
// speedup vs baseline: 1.0241x; 1.0241x over previous
#include <cuda_runtime.h>
#include <cuda_bf16.h>

#define EPS_SIGN 1e-8f
#define EPS_NORM 1e-9f

// Padded xyz as float4: each node gather = ONE LDG.128.
#define XYZ4_CAP 131072
__device__ float4 g_xyz4[XYZ4_CAP];

// Vectorized repack: thread j handles nodes 4j..4j+3 via 3 float4 loads.
__global__ __launch_bounds__(256)
void repack_xyz4_kernel(const float4* __restrict__ xyz4, int N4, int N)
{
    int j = blockIdx.x * blockDim.x + threadIdx.x;
    if (j < N4) {
        float4 f0 = xyz4[3*j + 0];   // x0 y0 z0 x1
        float4 f1 = xyz4[3*j + 1];   // y1 z1 x2 y2
        float4 f2 = xyz4[3*j + 2];   // z2 x3 y3 z3
        g_xyz4[4*j + 0] = make_float4(f0.x, f0.y, f0.z, 0.0f);
        g_xyz4[4*j + 1] = make_float4(f0.w, f1.x, f1.y, 0.0f);
        g_xyz4[4*j + 2] = make_float4(f1.z, f1.w, f2.x, 0.0f);
        g_xyz4[4*j + 3] = make_float4(f2.y, f2.z, f2.w, 0.0f);
    } else if (j == N4) {
        // tail nodes 4*N4 .. N-1 (scalar)
        const float* xyz = (const float*)xyz4;
        for (int i = 4 * N4; i < N; i++)
            g_xyz4[i] = make_float4(xyz[3*i+0], xyz[3*i+1], xyz[3*i+2], 0.0f);
    }
}

// 1 edge/thread; full warps write vec via shuffle-coalesced passes:
// store wavefronts per 32 edges drop 9 -> 3.
__global__ __launch_bounds__(256)
void edge_min_image_kernel(const int*   __restrict__ src,
                           const int*   __restrict__ dst,
                           const float* __restrict__ cell,
                           float* __restrict__ out_dis,
                           float* __restrict__ out_vec,
                           int E)
{
    int tid       = blockIdx.x * blockDim.x + threadIdx.x;
    int lane      = threadIdx.x & 31;
    int warp_base = tid - lane;          // first edge of this warp
    if (warp_base >= E) return;

    bool full_warp = (warp_base + 32 <= E);
    int  e         = warp_base + lane;
    bool active    = (e < E);

    const float cx = __ldg(&cell[0]);
    const float cy = __ldg(&cell[1]);
    const float cz = __ldg(&cell[2]);

    float vx = 0.f, vy = 0.f, vz = 0.f, dis = 0.f;

    if (active) {
        int si = __ldg(&src[e]);
        int di = __ldg(&dst[e]);

        float4 a = g_xyz4[si];
        float4 b = g_xyz4[di];

        float dx = a.x - b.x;
        float dy = a.y - b.y;
        float dz = a.z - b.z;

        float ax = fabsf(dx), ay = fabsf(dy), az = fabsf(dz);

        float mx = fminf(cx - ax, ax);
        float my = fminf(cy - ay, ay);
        float mz = fminf(cz - az, az);

        float k2x = (fabsf(mx) == ax) ? 1.0f : -1.0f;
        float k2y = (fabsf(my) == ay) ? 1.0f : -1.0f;
        float k2z = (fabsf(mz) == az) ? 1.0f : -1.0f;

        float sx = (dx + EPS_SIGN >= 0.0f) ? 1.0f : -1.0f;
        float sy = (dy + EPS_SIGN >= 0.0f) ? 1.0f : -1.0f;
        float sz = (dz + EPS_SIGN >= 0.0f) ? 1.0f : -1.0f;

        vx = mx * (k2x * sx);
        vy = my * (k2y * sy);
        vz = mz * (k2z * sz);

        float ex = dx + EPS_NORM, ey = dy + EPS_NORM, ez = dz + EPS_NORM;
        dis = sqrtf(ex*ex + ey*ey + ez*ez);

        out_dis[e] = dis;   // coalesced, 1 wf/warp
    }

    if (full_warp) {
        // vec span for this warp: out_vec[3*warp_base .. +96), 3 coalesced passes
        float* bp = out_vec + 3 * warp_base;
        #pragma unroll
        for (int p = 0; p < 3; p++) {
            int g  = p * 32 + lane;      // 0..95
            int sl = g / 3;              // owning lane
            int c  = g - 3 * sl;         // component
            float a0 = __shfl_sync(0xffffffffu, vx, sl);
            float a1 = __shfl_sync(0xffffffffu, vy, sl);
            float a2 = __shfl_sync(0xffffffffu, vz, sl);
            float v  = (c == 0) ? a0 : ((c == 1) ? a1 : a2);
            bp[g] = v;                   // lane-consecutive: 1 wf per pass
        }
    } else if (active) {
        float* vp = out_vec + 3 * e;
        vp[0] = vx; vp[1] = vy; vp[2] = vz;
    }
}

// Fallback (N > scratch capacity): scalar-gather path, always correct.
__global__ __launch_bounds__(256)
void edge_min_image_fallback(const float* __restrict__ xyz,
                             const int*   __restrict__ src,
                             const int*   __restrict__ dst,
                             const float* __restrict__ cell,
                             float* __restrict__ out_dis,
                             float* __restrict__ out_vec,
                             int E)
{
    const float cx = __ldg(&cell[0]);
    const float cy = __ldg(&cell[1]);
    const float cz = __ldg(&cell[2]);

    int e = blockIdx.x * blockDim.x + threadIdx.x;
    if (e >= E) return;

    int si = src[e], di = dst[e];
    float dx = xyz[3*si+0] - xyz[3*di+0];
    float dy = xyz[3*si+1] - xyz[3*di+1];
    float dz = xyz[3*si+2] - xyz[3*di+2];

    float ax = fabsf(dx), ay = fabsf(dy), az = fabsf(dz);
    float mx = fminf(cx - ax, ax);
    float my = fminf(cy - ay, ay);
    float mz = fminf(cz - az, az);
    float k2x = (fabsf(mx) == ax) ? 1.0f : -1.0f;
    float k2y = (fabsf(my) == ay) ? 1.0f : -1.0f;
    float k2z = (fabsf(mz) == az) ? 1.0f : -1.0f;
    float sx = (dx + EPS_SIGN >= 0.0f) ? 1.0f : -1.0f;
    float sy = (dy + EPS_SIGN >= 0.0f) ? 1.0f : -1.0f;
    float sz = (dz + EPS_SIGN >= 0.0f) ? 1.0f : -1.0f;

    out_vec[3*e+0] = mx * (k2x * sx);
    out_vec[3*e+1] = my * (k2y * sy);
    out_vec[3*e+2] = mz * (k2z * sz);

    float ex = dx + EPS_NORM, ey = dy + EPS_NORM, ez = dz + EPS_NORM;
    out_dis[e] = sqrtf(ex*ex + ey*ey + ez*ez);
}

extern "C" void kernel_launch(void* const* d_in, const int* in_sizes, int n_in,
                              void* d_out, int out_size)
{
    const float* xyz  = (const float*)d_in[0];
    const int*   src  = (const int*)  d_in[1];
    const int*   dst  = (const int*)  d_in[2];
    const float* cell = (const float*)d_in[3];

    int N = in_sizes[0] / 3;   // xyz rows
    int E = in_sizes[1];       // number of edges

    float* out_dis = (float*)d_out;   // [E]
    float* out_vec = out_dis + E;     // [E,3] row-major

    const int t = 256;
    if (N <= XYZ4_CAP) {
        int N4 = N / 4;
        int rthreads = N4 + 1;                     // +1 thread covers the tail
        repack_xyz4_kernel<<<(rthreads + t - 1) / t, t>>>(
            (const float4*)xyz, N4, N);
        edge_min_image_kernel<<<(E + t - 1) / t, t>>>(src, dst, cell,
                                                      out_dis, out_vec, E);
    } else {
        edge_min_image_fallback<<<(E + t - 1) / t, t>>>(xyz, src, dst, cell,
                                                        out_dis, out_vec, E);
    }
}

// round 8
// speedup vs baseline: 1.0808x; 1.0554x over previous
#include <cuda_runtime.h>
#include <cuda_bf16.h>

#define EPS_SIGN 1e-8f
#define EPS_NORM 1e-9f

// Padded xyz as float4: each node gather = ONE LDG.128.
#define XYZ4_CAP 131072
__device__ float4 g_xyz4[XYZ4_CAP];

// Vectorized repack: thread j handles nodes 4j..4j+3 via 3 float4 loads.
__global__ __launch_bounds__(256)
void repack_xyz4_kernel(const float4* __restrict__ xyz4, int N4, int N)
{
    int j = blockIdx.x * blockDim.x + threadIdx.x;
    if (j < N4) {
        float4 f0 = xyz4[3*j + 0];   // x0 y0 z0 x1
        float4 f1 = xyz4[3*j + 1];   // y1 z1 x2 y2
        float4 f2 = xyz4[3*j + 2];   // z2 x3 y3 z3
        g_xyz4[4*j + 0] = make_float4(f0.x, f0.y, f0.z, 0.0f);
        g_xyz4[4*j + 1] = make_float4(f0.w, f1.x, f1.y, 0.0f);
        g_xyz4[4*j + 2] = make_float4(f1.z, f1.w, f2.x, 0.0f);
        g_xyz4[4*j + 3] = make_float4(f2.y, f2.z, f2.w, 0.0f);
    } else if (j == N4) {
        const float* xyz = (const float*)xyz4;
        for (int i = 4 * N4; i < N; i++)
            g_xyz4[i] = make_float4(xyz[3*i+0], xyz[3*i+1], xyz[3*i+2], 0.0f);
    }
}

struct EdgeOut { float vx, vy, vz, dis; };

__device__ __forceinline__ EdgeOut edge_compute(int si, int di,
                                                float cx, float cy, float cz)
{
    float4 a = g_xyz4[si];
    float4 b = g_xyz4[di];

    float dx = a.x - b.x, dy = a.y - b.y, dz = a.z - b.z;
    float ax = fabsf(dx), ay = fabsf(dy), az = fabsf(dz);

    float mx = fminf(cx - ax, ax);
    float my = fminf(cy - ay, ay);
    float mz = fminf(cz - az, az);

    float k2x = (fabsf(mx) == ax) ? 1.0f : -1.0f;
    float k2y = (fabsf(my) == ay) ? 1.0f : -1.0f;
    float k2z = (fabsf(mz) == az) ? 1.0f : -1.0f;

    float sx = (dx + EPS_SIGN >= 0.0f) ? 1.0f : -1.0f;
    float sy = (dy + EPS_SIGN >= 0.0f) ? 1.0f : -1.0f;
    float sz = (dz + EPS_SIGN >= 0.0f) ? 1.0f : -1.0f;

    EdgeOut o;
    o.vx = mx * (k2x * sx);
    o.vy = my * (k2y * sy);
    o.vz = mz * (k2z * sz);
    float ex = dx + EPS_NORM, ey = dy + EPS_NORM, ez = dz + EPS_NORM;
    o.dis = sqrtf(ex*ex + ey*ey + ez*ez);
    return o;
}

// 2 edges/thread (warp-strided e, e+32): 4 independent gather LDG.128s in
// flight per thread keeps l1tex saturated; shuffle-coalesced vec stores keep
// store wavefronts at 3 per 32 edges. 192-float vec span splits at 96=3*32,
// so passes 0-2 use slot 0, passes 3-5 slot 1.
__global__ __launch_bounds__(256)
void edge_min_image_kernel(const int*   __restrict__ src,
                           const int*   __restrict__ dst,
                           const float* __restrict__ cell,
                           float* __restrict__ out_dis,
                           float* __restrict__ out_vec,
                           int E)
{
    int tid  = blockIdx.x * blockDim.x + threadIdx.x;
    int lane = threadIdx.x & 31;
    int base = ((tid >> 5) << 6);        // 64 edges per warp
    if (base >= E) return;

    const float cx = __ldg(&cell[0]);
    const float cy = __ldg(&cell[1]);
    const float cz = __ldg(&cell[2]);

    int e0 = base + lane;
    int e1 = base + 32 + lane;

    if (base + 64 <= E) {
        // ---- full warp: everything vector/coalesced ----
        int s0 = __ldg(&src[e0]);
        int s1 = __ldg(&src[e1]);
        int d0 = __ldg(&dst[e0]);
        int d1 = __ldg(&dst[e1]);

        EdgeOut r0 = edge_compute(s0, d0, cx, cy, cz);
        EdgeOut r1 = edge_compute(s1, d1, cx, cy, cz);

        out_dis[e0] = r0.dis;
        out_dis[e1] = r1.dis;

        float* bp = out_vec + 3 * base;  // 192-float span
        #pragma unroll
        for (int p = 0; p < 3; p++) {    // slot 0: floats [0,96)
            int g  = p * 32 + lane;
            int sl = g / 3;
            int c  = g - 3 * sl;
            float a0 = __shfl_sync(0xffffffffu, r0.vx, sl);
            float a1 = __shfl_sync(0xffffffffu, r0.vy, sl);
            float a2 = __shfl_sync(0xffffffffu, r0.vz, sl);
            bp[g] = (c == 0) ? a0 : ((c == 1) ? a1 : a2);
        }
        #pragma unroll
        for (int p = 0; p < 3; p++) {    // slot 1: floats [96,192)
            int g  = p * 32 + lane;
            int sl = g / 3;
            int c  = g - 3 * sl;
            float a0 = __shfl_sync(0xffffffffu, r1.vx, sl);
            float a1 = __shfl_sync(0xffffffffu, r1.vy, sl);
            float a2 = __shfl_sync(0xffffffffu, r1.vz, sl);
            bp[96 + g] = (c == 0) ? a0 : ((c == 1) ? a1 : a2);
        }
    } else {
        // ---- tail warp: per-edge scalar ----
        #pragma unroll
        for (int k = 0; k < 2; k++) {
            int e = base + 32 * k + lane;
            if (e < E) {
                EdgeOut r = edge_compute(__ldg(&src[e]), __ldg(&dst[e]),
                                         cx, cy, cz);
                out_dis[e] = r.dis;
                float* vp = out_vec + 3 * e;
                vp[0] = r.vx; vp[1] = r.vy; vp[2] = r.vz;
            }
        }
    }
}

// Fallback (N > scratch capacity): scalar-gather path, always correct.
__global__ __launch_bounds__(256)
void edge_min_image_fallback(const float* __restrict__ xyz,
                             const int*   __restrict__ src,
                             const int*   __restrict__ dst,
                             const float* __restrict__ cell,
                             float* __restrict__ out_dis,
                             float* __restrict__ out_vec,
                             int E)
{
    const float cx = __ldg(&cell[0]);
    const float cy = __ldg(&cell[1]);
    const float cz = __ldg(&cell[2]);

    int e = blockIdx.x * blockDim.x + threadIdx.x;
    if (e >= E) return;

    int si = src[e], di = dst[e];
    float dx = xyz[3*si+0] - xyz[3*di+0];
    float dy = xyz[3*si+1] - xyz[3*di+1];
    float dz = xyz[3*si+2] - xyz[3*di+2];

    float ax = fabsf(dx), ay = fabsf(dy), az = fabsf(dz);
    float mx = fminf(cx - ax, ax);
    float my = fminf(cy - ay, ay);
    float mz = fminf(cz - az, az);
    float k2x = (fabsf(mx) == ax) ? 1.0f : -1.0f;
    float k2y = (fabsf(my) == ay) ? 1.0f : -1.0f;
    float k2z = (fabsf(mz) == az) ? 1.0f : -1.0f;
    float sx = (dx + EPS_SIGN >= 0.0f) ? 1.0f : -1.0f;
    float sy = (dy + EPS_SIGN >= 0.0f) ? 1.0f : -1.0f;
    float sz = (dz + EPS_SIGN >= 0.0f) ? 1.0f : -1.0f;

    out_vec[3*e+0] = mx * (k2x * sx);
    out_vec[3*e+1] = my * (k2y * sy);
    out_vec[3*e+2] = mz * (k2z * sz);

    float ex = dx + EPS_NORM, ey = dy + EPS_NORM, ez = dz + EPS_NORM;
    out_dis[e] = sqrtf(ex*ex + ey*ey + ez*ez);
}

extern "C" void kernel_launch(void* const* d_in, const int* in_sizes, int n_in,
                              void* d_out, int out_size)
{
    const float* xyz  = (const float*)d_in[0];
    const int*   src  = (const int*)  d_in[1];
    const int*   dst  = (const int*)  d_in[2];
    const float* cell = (const float*)d_in[3];

    int N = in_sizes[0] / 3;   // xyz rows
    int E = in_sizes[1];       // number of edges

    float* out_dis = (float*)d_out;   // [E]
    float* out_vec = out_dis + E;     // [E,3] row-major

    const int t = 256;
    if (N <= XYZ4_CAP) {
        int N4 = N / 4;
        int rthreads = N4 + 1;
        repack_xyz4_kernel<<<(rthreads + t - 1) / t, t>>>(
            (const float4*)xyz, N4, N);
        // 64 edges per warp -> E/64 warps -> /8 warps per block
        int warps  = (E + 63) / 64;
        int blocks = (warps + 7) / 8;
        edge_min_image_kernel<<<blocks, t>>>(src, dst, cell,
                                             out_dis, out_vec, E);
    } else {
        edge_min_image_fallback<<<(E + t - 1) / t, t>>>(xyz, src, dst, cell,
                                                        out_dis, out_vec, E);
    }
}